// round 13
// baseline (speedup 1.0000x reference)
#include <cuda_runtime.h>
#include <cuda_fp16.h>
#include <cstdint>

#define PNUM 8
#define DDIM 512
#define ADIM 64
#define XDIM 576
#define HDIM 1024
#define BCAP 16384
#define MAXT 136

// ---------------- device scratch ----------------
__device__ int d_cursor[PNUM];
__device__ int d_is64;
__device__ int d_qhead;
__device__ int d_ready[MAXT];
__device__ int d_gflag[MAXT];
__device__ int d_w1done;
__device__ int d_w2done;
__device__ int d_row_id[PNUM * BCAP];
__device__ __align__(128) __half d_xbuf[(size_t)MAXT * 128 * XDIM];
__device__ __align__(128) __half d_hbuf[(size_t)MAXT * 128 * HDIM];
__device__ __align__(128) __half d_w1h[(size_t)PNUM * XDIM * HDIM];   // [p][k][n]
__device__ __align__(128) __half d_w2h[(size_t)PNUM * HDIM * DDIM];   // [p][k][n]

// ---------------- helpers ----------------
__device__ __forceinline__ void cpasync16(uint32_t dst, const void* src) {
    asm volatile("cp.async.cg.shared.global [%0], [%1], 16;\n"
                 :: "r"(dst), "l"(src) : "memory");
}
#define CP_COMMIT() asm volatile("cp.async.commit_group;\n" ::: "memory")
#define CP_WAIT(n)  asm volatile("cp.async.wait_group " #n ";\n" ::: "memory")

__device__ __forceinline__ uint32_t smem_u32(const void* p) {
    uint32_t a;
    asm("{ .reg .u64 t; cvta.to.shared.u64 t, %1; cvt.u32.u64 %0, t; }" : "=r"(a) : "l"(p));
    return a;
}
__device__ __forceinline__ void ldsm4(uint32_t* r, uint32_t addr) {
    asm volatile("ldmatrix.sync.aligned.m8n8.x4.shared.b16 {%0,%1,%2,%3}, [%4];"
                 : "=r"(r[0]), "=r"(r[1]), "=r"(r[2]), "=r"(r[3]) : "r"(addr));
}
__device__ __forceinline__ void ldsm4t(uint32_t* r, uint32_t addr) {
    asm volatile("ldmatrix.sync.aligned.m8n8.x4.trans.shared.b16 {%0,%1,%2,%3}, [%4];"
                 : "=r"(r[0]), "=r"(r[1]), "=r"(r[2]), "=r"(r[3]) : "r"(addr));
}
__device__ __forceinline__ void mma_f16(float* c, const uint32_t* a, uint32_t b0, uint32_t b1) {
    asm volatile(
        "mma.sync.aligned.m16n8k16.row.col.f32.f16.f16.f32 "
        "{%0,%1,%2,%3}, {%4,%5,%6,%7}, {%8,%9}, {%0,%1,%2,%3};"
        : "+f"(c[0]), "+f"(c[1]), "+f"(c[2]), "+f"(c[3])
        : "r"(a[0]), "r"(a[1]), "r"(a[2]), "r"(a[3]), "r"(b0), "r"(b1));
}
__device__ __forceinline__ int get_pidx(const void* pi, int b) {
    if (d_is64) return (int)(((const long long*)pi)[b]);
    return ((const int*)pi)[b];
}
__device__ __forceinline__ void spin_ge(const int* flag, int target) {
    int v;
    do {
        asm volatile("ld.acquire.gpu.global.b32 %0, [%1];"
                     : "=r"(v) : "l"(flag) : "memory");
        if (v < target) __nanosleep(64);
    } while (v < target);
}

struct Meta { int p, vrows, ridbase; };
__device__ __forceinline__ Meta tile_meta(int t) {
    int acc = 0, p = -1, lt = 0, c = 0;
#pragma unroll
    for (int q = 0; q < PNUM; q++) {
        int cq = d_cursor[q];
        int nt = (cq + 127) >> 7;
        if (p < 0 && t < acc + nt) { p = q; lt = t - acc; c = cq; }
        acc += nt;
    }
    Meta m; m.p = p;
    if (p >= 0) {
        int rem = c - lt * 128;
        m.vrows = rem < 128 ? rem : 128;
        m.ridbase = p * BCAP + lt * 128;
    } else { m.vrows = 0; m.ridbase = 0; }
    return m;
}

// ---------------- setup ----------------
__global__ __launch_bounds__(256) void k_init(const int* pi32, int B) {
    int t = threadIdx.x;
    if (t < PNUM) d_cursor[t] = 0;
    if (t == 0) { d_qhead = 0; d_w1done = 0; d_w2done = 0; }
    for (int i = t; i < MAXT; i += 256) { d_ready[i] = 0; d_gflag[i] = 0; }
    if (t < 32) {
        int n = B < 64 ? B : 64;
        int bad = 0;
#pragma unroll
        for (int r = 0; r < 2; r++) {
            int i = t + 32 * r;
            if (i < n) {
                int lo = pi32[2 * i], hi = pi32[2 * i + 1];
                bad |= (hi != 0) || (lo < 0) || (lo >= PNUM);
            }
        }
        unsigned m = __ballot_sync(0xFFFFFFFF, bad);
        if (t == 0) d_is64 = (m == 0) ? 1 : 0;
    }
}

// two-phase scatter
__global__ __launch_bounds__(256) void k_scan(const void* __restrict__ pi, int B) {
    __shared__ int cnt[PNUM], base[PNUM];
    int tid = threadIdx.x;
    if (tid < PNUM) cnt[tid] = 0;
    __syncthreads();
    int b = blockIdx.x * 256 + tid;
    int p = 0, pos = 0;
    if (b < B) {
        p = get_pidx(pi, b);
        pos = atomicAdd(&cnt[p], 1);
    }
    __syncthreads();
    if (tid < PNUM) base[tid] = atomicAdd(&d_cursor[tid], cnt[tid]);
    __syncthreads();
    if (b < B) d_row_id[p * BCAP + base[p] + pos] = b;
}

// ---------------- SMEM layout ----------------
#define AROWB   80
#define ABYTES  (128 * AROWB)         // 10240
#define BROWB   272
#define BBYTES  (32 * BROWB)          // 8704
#define STAGE   (ABYTES + BBYTES)     // 18944
#define NSTG    5
#define SMEM_TOTAL (NSTG * STAGE)     // 94720

#define W1F4 ((PNUM * XDIM * HDIM) / 4)   // 1179648
#define W2F4 ((PNUM * HDIM * DDIM) / 4)   // 1048576
#define NW1  144                          // 8192 float4 per item
#define NW2  128

// ---------------- prep items ----------------
__device__ __forceinline__ void run_gather(
    int t, const float* __restrict__ latents, const float* __restrict__ actions,
    int* rid_s)
{
    const int tid = threadIdx.x;
    __shared__ Meta gm;
    if (tid == 0) gm = tile_meta(t);
    __syncthreads();
    if (tid < 128) rid_s[tid] = (tid < gm.vrows) ? d_row_id[gm.ridbase + tid] : -1;
    __syncthreads();
    __half* xb = d_xbuf + (size_t)t * 128 * XDIM;
#pragma unroll
    for (int tt = 0; tt < 36; tt++) {
        int j = tid + tt * 256;              // 128 rows * 72 segs of 8 floats
        int row = j / 72, s = j % 72;
        int b = rid_s[row];
        float4 v0 = make_float4(0.f, 0.f, 0.f, 0.f), v1 = v0;
        if (b >= 0) {
            const float* src = (s < 64) ? latents + (size_t)b * DDIM + s * 8
                                        : actions + (size_t)b * ADIM + (s - 64) * 8;
            v0 = *(const float4*)(src); v1 = *(const float4*)(src + 4);
        }
        __half2 h0 = __floats2half2_rn(v0.x, v0.y);
        __half2 h1 = __floats2half2_rn(v0.z, v0.w);
        __half2 h2 = __floats2half2_rn(v1.x, v1.y);
        __half2 h3 = __floats2half2_rn(v1.z, v1.w);
        __half2* dst = (__half2*)(xb + (size_t)row * XDIM + s * 8);
        dst[0] = h0; dst[1] = h1; dst[2] = h2; dst[3] = h3;
    }
    __threadfence();
    __syncthreads();
    if (tid == 0) atomicAdd(&d_gflag[t], 1);
}

template <int WHICH>
__device__ __forceinline__ void run_wconv(int item, const float4* __restrict__ W)
{
    constexpr int LIM = (WHICH == 1) ? W1F4 : W2F4;
    __half* const wh = (WHICH == 1) ? d_w1h : d_w2h;
    size_t i0 = (size_t)item * 8192 + threadIdx.x;
#pragma unroll
    for (int u = 0; u < 32; u++) {
        size_t i = i0 + (size_t)u * 256;
        if (i < (size_t)LIM) {
            float4 v = W[i];
            __half2 h0 = __floats2half2_rn(v.x, v.y);
            __half2 h1 = __floats2half2_rn(v.z, v.w);
            uint2 o = make_uint2(*(uint32_t*)&h0, *(uint32_t*)&h1);
            *(uint2*)(wh + i * 4) = o;
        }
    }
    __threadfence();
    __syncthreads();
    if (threadIdx.x == 0)
        atomicAdd((WHICH == 1) ? &d_w1done : &d_w2done, 1);
}

// ---------------- one GEMM item: 128(m) x 128(n), full K ----------------
template <int LAYER>
__device__ __forceinline__ void run_item(
    int t, int n0, const float* __restrict__ bias, float* __restrict__ out,
    uint32_t sb, int* rid_s)
{
    constexpr int KDIM = (LAYER == 1) ? XDIM : HDIM;
    constexpr int NDIM = (LAYER == 1) ? HDIM : DDIM;
    constexpr int KT   = KDIM / 32;
    const int tid = threadIdx.x;

    __shared__ Meta sm;
    if (tid == 0) sm = tile_meta(t);
    if (LAYER == 1) {
        if (tid == 32) spin_ge(&d_gflag[t], 1);
        if (tid == 64) spin_ge(&d_w1done, NW1);
    } else {
        if (tid == 32) spin_ge(&d_ready[t], 8);
        if (tid == 64) spin_ge(&d_w2done, NW2);
    }
    __syncthreads();
    const int p = sm.p;
    if (LAYER == 2 && tid < 128)
        rid_s[tid] = (tid < sm.vrows) ? d_row_id[sm.ridbase + tid] : -1;
    const int row0 = t * 128;

    // ---- streaming pointers ----
    const int arow = tid >> 2, aseg = tid & 3;
    const __half* aptr = ((LAYER == 1) ? d_xbuf : d_hbuf)
                         + (size_t)(row0 + arow) * KDIM + aseg * 8;
    const uint32_t adst = (uint32_t)arow * AROWB + aseg * 16;
    const int brow = tid >> 4, bseg = tid & 15;
    const __half* bptr = ((LAYER == 1) ? d_w1h + (size_t)p * XDIM * HDIM
                                       : d_w2h + (size_t)p * HDIM * DDIM)
                         + (size_t)brow * NDIM + n0 + bseg * 8;
    const uint32_t bdst = (uint32_t)brow * BROWB + bseg * 16;

    auto load = [&](int slot) {
        const uint32_t ab = sb + slot * STAGE;
#pragma unroll
        for (int tt = 0; tt < 2; tt++)
            cpasync16(ab + adst + tt * (64 * AROWB), aptr + (size_t)tt * 64 * KDIM);
#pragma unroll
        for (int tt = 0; tt < 2; tt++)
            cpasync16(ab + ABYTES + bdst + tt * (16 * BROWB), bptr + (size_t)tt * 16 * NDIM);
        CP_COMMIT();
        aptr += 32;
        bptr += (size_t)32 * NDIM;
    };

    // ---- fragment geometry: 2(m) x 4(n) warps, 64x32 warp tiles ----
    const int lane = tid & 31, warp = tid >> 5;
    const int wm = warp >> 2, wn = warp & 3;
    const int g = lane >> 2, tq = lane & 3;
    const uint32_t ao = (uint32_t)(wm * 64) * AROWB
                      + (uint32_t)(lane & 15) * AROWB + (uint32_t)(lane & 16);
    const uint32_t bo = (uint32_t)((lane & 7) + ((lane >> 3) & 1) * 8) * BROWB
                      + (uint32_t)((lane >> 4) & 1) * 16
                      + (uint32_t)(wn * 32) * 2;

    float acc[4][4][4];
#pragma unroll
    for (int i = 0; i < 4; i++)
#pragma unroll
        for (int j = 0; j < 4; j++)
#pragma unroll
            for (int q = 0; q < 4; q++) acc[i][j][q] = 0.f;

    load(0); load(1); load(2); load(3);

    int slot = 0, lslot = 4;
    for (int c = 0; c < KT; c++) {
        if (c + 4 <= KT)      CP_WAIT(3);
        else if (c + 3 == KT) CP_WAIT(2);
        else if (c + 2 == KT) CP_WAIT(1);
        else                  CP_WAIT(0);
        __syncthreads();

        if (c + 4 < KT) {
            load(lslot);
            lslot = (lslot == 4) ? 0 : lslot + 1;
        }

        const uint32_t Ab = sb + slot * STAGE;
        const uint32_t Bb = Ab + ABYTES;
#pragma unroll
        for (int ks = 0; ks < 2; ks++) {
            uint32_t a[4][4], b[2][4];
#pragma unroll
            for (int i = 0; i < 4; i++)
                ldsm4(a[i], Ab + ao + (uint32_t)(i * 16 * AROWB + ks * 32));
#pragma unroll
            for (int jj = 0; jj < 2; jj++)
                ldsm4t(b[jj], Bb + bo + (uint32_t)(ks * 16 * BROWB + jj * 32));
#pragma unroll
            for (int i = 0; i < 4; i++)
#pragma unroll
                for (int jj = 0; jj < 2; jj++) {
                    mma_f16(acc[i][2 * jj],     a[i], b[jj][0], b[jj][1]);
                    mma_f16(acc[i][2 * jj + 1], a[i], b[jj][2], b[jj][3]);
                }
        }
        slot = (slot == 4) ? 0 : slot + 1;
    }

    // ---- epilogue ----
    const float* bp = bias + p * NDIM + n0;
    if (LAYER == 1) {
        __half* hb = d_hbuf + (size_t)row0 * HDIM + n0;
#pragma unroll
        for (int j = 0; j < 4; j++) {
            int col = wn * 32 + j * 8 + 2 * tq;
            float bx = bp[col], by = bp[col + 1];
#pragma unroll
            for (int i = 0; i < 4; i++) {
                int r0 = wm * 64 + i * 16 + g;
                __half2 v0 = __floats2half2_rn(fmaxf(acc[i][j][0] + bx, 0.f),
                                               fmaxf(acc[i][j][1] + by, 0.f));
                __half2 v1 = __floats2half2_rn(fmaxf(acc[i][j][2] + bx, 0.f),
                                               fmaxf(acc[i][j][3] + by, 0.f));
                *(__half2*)(hb + (size_t)r0 * HDIM + col)       = v0;
                *(__half2*)(hb + (size_t)(r0 + 8) * HDIM + col) = v1;
            }
        }
        __threadfence();
        __syncthreads();
        if (tid == 0) atomicAdd(&d_ready[t], 1);
    } else {
#pragma unroll
        for (int i = 0; i < 4; i++) {
            int r0 = wm * 64 + i * 16 + g;
            int b0 = rid_s[r0], b1i = rid_s[r0 + 8];
#pragma unroll
            for (int j = 0; j < 4; j++) {
                int col = wn * 32 + j * 8 + 2 * tq;
                float bx = bp[col], by = bp[col + 1];
                if (b0 >= 0)
                    *(float2*)(out + (size_t)b0 * DDIM + n0 + col) =
                        make_float2(acc[i][j][0] + bx, acc[i][j][1] + by);
                if (b1i >= 0)
                    *(float2*)(out + (size_t)b1i * DDIM + n0 + col) =
                        make_float2(acc[i][j][2] + bx, acc[i][j][3] + by);
            }
        }
    }
}

// ---------------- persistent everything-kernel ----------------
__global__ __launch_bounds__(256, 2) void k_all(
    const float* __restrict__ latents, const float* __restrict__ actions,
    const float4* __restrict__ W1, const float4* __restrict__ W2,
    const float* __restrict__ b1, const float* __restrict__ b2,
    float* __restrict__ out)
{
    extern __shared__ char smem[];
    __shared__ int rid_s[128];
    __shared__ int s_item;
    const uint32_t sb = smem_u32(smem);
    const int tid = threadIdx.x;

    int nt = 0;
#pragma unroll
    for (int q = 0; q < PNUM; q++) nt += (d_cursor[q] + 127) >> 7;
    const int NG    = nt;
    const int BW1   = NG;
    const int BW2   = BW1 + NW1;
    const int BL1   = BW2 + NW2;
    const int BL2   = BL1 + nt * 8;
    const int NTOT  = BL2 + nt * 4;

    while (true) {
        if (tid == 0) s_item = atomicAdd(&d_qhead, 1);
        __syncthreads();
        const int item = s_item;
        __syncthreads();
        if (item >= NTOT) return;
        if (item < NG) {
            run_gather(item, latents, actions, rid_s);
        } else if (item < BW2) {
            run_wconv<1>(item - BW1, W1);
        } else if (item < BL1) {
            run_wconv<2>(item - BW2, W2);
        } else if (item < BL2) {
            int j = item - BL1;
            run_item<1>(j >> 3, (j & 7) * 128, b1, out, sb, rid_s);
        } else {
            int j = item - BL2;
            run_item<2>(j >> 2, (j & 3) * 128, b2, out, sb, rid_s);
        }
        __syncthreads();
    }
}

// ---------------- launch ----------------
extern "C" void kernel_launch(void* const* d_in, const int* in_sizes, int n_in,
                              void* d_out, int out_size)
{
    const float* latents = (const float*)d_in[0];
    const float* actions = (const float*)d_in[1];
    const void*  pidx    = d_in[2];
    const float* W1      = (const float*)d_in[3];
    const float* b1      = (const float*)d_in[4];
    const float* W2      = (const float*)d_in[5];
    const float* b2      = (const float*)d_in[6];
    float*       out     = (float*)d_out;

    int B = in_sizes[0] / DDIM;               // 16384

    int nsm = 148;
    cudaDeviceGetAttribute(&nsm, cudaDevAttrMultiProcessorCount, 0);

    cudaFuncSetAttribute(k_all, cudaFuncAttributeMaxDynamicSharedMemorySize, SMEM_TOTAL);

    k_init<<<1, 256>>>((const int*)pidx, B);
    k_scan<<<(B + 255) / 256, 256>>>(pidx, B);
    k_all<<<2 * nsm, 256, SMEM_TOTAL>>>(latents, actions,
                                        (const float4*)W1, (const float4*)W2,
                                        b1, b2, out);
}

// round 14
// speedup vs baseline: 1.0588x; 1.0588x over previous
#include <cuda_runtime.h>
#include <cuda_fp16.h>
#include <cstdint>

#define PNUM 8
#define DDIM 512
#define ADIM 64
#define XDIM 576
#define HDIM 1024
#define BCAP 16384
#define MAXT 136

// ---------------- device scratch (zero-initialized at load; k_fused re-zeros at exit) ----------------
__device__ int d_cursor[PNUM];
__device__ int d_qhead;
__device__ int d_done;
__device__ int d_scandone;
__device__ int d_ready[MAXT];
__device__ int d_row_id[PNUM * BCAP];
__device__ __align__(128) __half d_xbuf[(size_t)MAXT * 128 * XDIM];
__device__ __align__(128) __half d_hbuf[(size_t)MAXT * 128 * HDIM];
__device__ __align__(128) __half d_w1h[(size_t)PNUM * XDIM * HDIM];   // [p][k][n]
__device__ __align__(128) __half d_w2h[(size_t)PNUM * HDIM * DDIM];   // [p][k][n]

// ---------------- helpers ----------------
__device__ __forceinline__ void cpasync16(uint32_t dst, const void* src) {
    asm volatile("cp.async.cg.shared.global [%0], [%1], 16;\n"
                 :: "r"(dst), "l"(src) : "memory");
}
#define CP_COMMIT() asm volatile("cp.async.commit_group;\n" ::: "memory")
#define CP_WAIT(n)  asm volatile("cp.async.wait_group " #n ";\n" ::: "memory")

__device__ __forceinline__ uint32_t smem_u32(const void* p) {
    uint32_t a;
    asm("{ .reg .u64 t; cvta.to.shared.u64 t, %1; cvt.u32.u64 %0, t; }" : "=r"(a) : "l"(p));
    return a;
}
__device__ __forceinline__ void ldsm4(uint32_t* r, uint32_t addr) {
    asm volatile("ldmatrix.sync.aligned.m8n8.x4.shared.b16 {%0,%1,%2,%3}, [%4];"
                 : "=r"(r[0]), "=r"(r[1]), "=r"(r[2]), "=r"(r[3]) : "r"(addr));
}
__device__ __forceinline__ void ldsm4t(uint32_t* r, uint32_t addr) {
    asm volatile("ldmatrix.sync.aligned.m8n8.x4.trans.shared.b16 {%0,%1,%2,%3}, [%4];"
                 : "=r"(r[0]), "=r"(r[1]), "=r"(r[2]), "=r"(r[3]) : "r"(addr));
}
__device__ __forceinline__ void mma_f16(float* c, const uint32_t* a, uint32_t b0, uint32_t b1) {
    asm volatile(
        "mma.sync.aligned.m16n8k16.row.col.f32.f16.f16.f32 "
        "{%0,%1,%2,%3}, {%4,%5,%6,%7}, {%8,%9}, {%0,%1,%2,%3};"
        : "+f"(c[0]), "+f"(c[1]), "+f"(c[2]), "+f"(c[3])
        : "r"(a[0]), "r"(a[1]), "r"(a[2]), "r"(a[3]), "r"(b0), "r"(b1));
}
__device__ __forceinline__ void spin_ge(const int* flag, int target) {
    int v;
    do {
        asm volatile("ld.acquire.gpu.global.b32 %0, [%1];"
                     : "=r"(v) : "l"(flag) : "memory");
        if (v < target) __nanosleep(64);
    } while (v < target);
}

struct Meta { int p, vrows, ridbase; };
__device__ __forceinline__ Meta tile_meta(int t) {
    int acc = 0, p = -1, lt = 0, c = 0;
#pragma unroll
    for (int q = 0; q < PNUM; q++) {
        int cq = d_cursor[q];
        int nt = (cq + 127) >> 7;
        if (p < 0 && t < acc + nt) { p = q; lt = t - acc; c = cq; }
        acc += nt;
    }
    Meta m; m.p = p;
    if (p >= 0) {
        int rem = c - lt * 128;
        m.vrows = rem < 128 ? rem : 128;
        m.ridbase = p * BCAP + lt * 128;
    } else { m.vrows = 0; m.ridbase = 0; }
    return m;
}

// ---------------- merged scan + prep ----------------
#define W1F4 ((PNUM * XDIM * HDIM) / 4)   // 1179648
#define W2F4 ((PNUM * HDIM * DDIM) / 4)   // 1048576
#define WF4  (W1F4 + W2F4)                // 2228224
#define GXBLK (4 * (BCAP / 128 + PNUM - 1))   // 540
#define W16BLK ((WF4 + 1023) / 1024)          // 2176

__global__ __launch_bounds__(256) void k_scanprep(
    const float* __restrict__ latents, const float* __restrict__ actions,
    const float4* __restrict__ W1, const float4* __restrict__ W2,
    const int* __restrict__ pi32, int B, int scanblk)
{
    const int tid = threadIdx.x;
    const int bid = blockIdx.x;

    if (bid < scanblk) {
        // ---- scan block: local is64 detection (fixed global window) + histogram scatter ----
        __shared__ int s_is64;
        __shared__ int cnt[PNUM], base[PNUM];
        if (tid < 32) {
            int n = B < 64 ? B : 64;
            int bad = 0;
#pragma unroll
            for (int r = 0; r < 2; r++) {
                int i = tid + 32 * r;
                if (i < n) {
                    int lo = pi32[2 * i], hi = pi32[2 * i + 1];
                    bad |= (hi != 0) || (lo < 0) || (lo >= PNUM);
                }
            }
            unsigned m = __ballot_sync(0xFFFFFFFF, bad);
            if (tid == 0) s_is64 = (m == 0) ? 1 : 0;
        }
        if (tid < PNUM) cnt[tid] = 0;
        __syncthreads();
        const int is64 = s_is64;
        int b = bid * 256 + tid;
        int p = 0, pos = 0;
        if (b < B) {
            p = is64 ? (int)(((const long long*)pi32)[b]) : pi32[b];
            pos = atomicAdd(&cnt[p], 1);
        }
        __syncthreads();
        if (tid < PNUM) base[tid] = atomicAdd(&d_cursor[tid], cnt[tid]);
        __syncthreads();
        if (b < B) d_row_id[p * BCAP + base[p] + pos] = b;
        __threadfence();
        __syncthreads();
        if (tid == 0) atomicAdd(&d_scandone, 1);
    } else if (bid < scanblk + W16BLK) {
        // ---- streaming fp32 -> fp16 weight convert (no deps) ----
        size_t i0 = ((size_t)(bid - scanblk) * 256 + tid) * 4;
#pragma unroll
        for (int u = 0; u < 4; u++) {
            size_t i = i0 + u;
            if (i >= WF4) return;
            float4 v;
            __half* dst;
            if (i < W1F4) { v = W1[i]; dst = d_w1h + i * 4; }
            else          { size_t j = i - W1F4; v = W2[j]; dst = d_w2h + j * 4; }
            __half2 h0 = __floats2half2_rn(v.x, v.y);
            __half2 h1 = __floats2half2_rn(v.z, v.w);
            uint2 o = make_uint2(*(uint32_t*)&h0, *(uint32_t*)&h1);
            *(uint2*)dst = o;
        }
    } else {
        // ---- x gather: 32 rows per block; waits for all scan blocks ----
        __shared__ int rid_s[32];
        __shared__ Meta sm;
        if (tid == 0) spin_ge(&d_scandone, scanblk);
        __syncthreads();
        int g = bid - scanblk - W16BLK;
        int t = g >> 2, q = g & 3;
        if (tid == 0) sm = tile_meta(t);
        __syncthreads();
        if (sm.p < 0) return;
        int rbase = q * 32;
        if (tid < 32)
            rid_s[tid] = (rbase + tid < sm.vrows) ? d_row_id[sm.ridbase + rbase + tid] : -1;
        __syncthreads();
        __half* xb = d_xbuf + ((size_t)t * 128 + rbase) * XDIM;
#pragma unroll
        for (int tt = 0; tt < 9; tt++) {
            int j = tid + tt * 256;
            int row = j / 72, s = j % 72;
            int b = rid_s[row];
            float4 v0 = make_float4(0.f, 0.f, 0.f, 0.f), v1 = v0;
            if (b >= 0) {
                const float* src = (s < 64) ? latents + (size_t)b * DDIM + s * 8
                                            : actions + (size_t)b * ADIM + (s - 64) * 8;
                v0 = *(const float4*)(src); v1 = *(const float4*)(src + 4);
            }
            __half2 h0 = __floats2half2_rn(v0.x, v0.y);
            __half2 h1 = __floats2half2_rn(v0.z, v0.w);
            __half2 h2 = __floats2half2_rn(v1.x, v1.y);
            __half2 h3 = __floats2half2_rn(v1.z, v1.w);
            __half2* dst = (__half2*)(xb + (size_t)row * XDIM + s * 8);
            dst[0] = h0; dst[1] = h1; dst[2] = h2; dst[3] = h3;
        }
    }
}

// ---------------- SMEM layout ----------------
#define AROWB   80
#define ABYTES  (128 * AROWB)         // 10240
#define BROWB   272
#define BBYTES  (32 * BROWB)          // 8704
#define STAGE   (ABYTES + BBYTES)     // 18944
#define NSTG    5
#define SMEM_TOTAL (NSTG * STAGE)     // 94720

// ---------------- one GEMM item: 128(m) x 128(n), full K (round-12 verbatim) ----------------
template <int LAYER>
__device__ __forceinline__ void run_item(
    int t, int n0, const float* __restrict__ bias, float* __restrict__ out,
    uint32_t sb, int* rid_s)
{
    constexpr int KDIM = (LAYER == 1) ? XDIM : HDIM;
    constexpr int NDIM = (LAYER == 1) ? HDIM : DDIM;
    constexpr int KT   = KDIM / 32;
    const int tid = threadIdx.x;

    __shared__ Meta sm;
    if (tid == 0) sm = tile_meta(t);
    if (LAYER == 2 && tid == 32) {   // wait for tile's 8 layer-1 items
        spin_ge(&d_ready[t], 8);
    }
    __syncthreads();
    const int p = sm.p;
    if (LAYER == 2 && tid < 128)
        rid_s[tid] = (tid < sm.vrows) ? d_row_id[sm.ridbase + tid] : -1;
    const int row0 = t * 128;

    // ---- streaming pointers ----
    const int arow = tid >> 2, aseg = tid & 3;
    const __half* aptr = ((LAYER == 1) ? d_xbuf : d_hbuf)
                         + (size_t)(row0 + arow) * KDIM + aseg * 8;
    const uint32_t adst = (uint32_t)arow * AROWB + aseg * 16;
    const int brow = tid >> 4, bseg = tid & 15;
    const __half* bptr = ((LAYER == 1) ? d_w1h + (size_t)p * XDIM * HDIM
                                       : d_w2h + (size_t)p * HDIM * DDIM)
                         + (size_t)brow * NDIM + n0 + bseg * 8;
    const uint32_t bdst = (uint32_t)brow * BROWB + bseg * 16;

    auto load = [&](int slot) {
        const uint32_t ab = sb + slot * STAGE;
#pragma unroll
        for (int tt = 0; tt < 2; tt++)
            cpasync16(ab + adst + tt * (64 * AROWB), aptr + (size_t)tt * 64 * KDIM);
#pragma unroll
        for (int tt = 0; tt < 2; tt++)
            cpasync16(ab + ABYTES + bdst + tt * (16 * BROWB), bptr + (size_t)tt * 16 * NDIM);
        CP_COMMIT();
        aptr += 32;
        bptr += (size_t)32 * NDIM;
    };

    // ---- fragment geometry: 2(m) x 4(n) warps, 64x32 warp tiles ----
    const int lane = tid & 31, warp = tid >> 5;
    const int wm = warp >> 2, wn = warp & 3;
    const int g = lane >> 2, tq = lane & 3;
    const uint32_t ao = (uint32_t)(wm * 64) * AROWB
                      + (uint32_t)(lane & 15) * AROWB + (uint32_t)(lane & 16);
    const uint32_t bo = (uint32_t)((lane & 7) + ((lane >> 3) & 1) * 8) * BROWB
                      + (uint32_t)((lane >> 4) & 1) * 16
                      + (uint32_t)(wn * 32) * 2;

    float acc[4][4][4];
#pragma unroll
    for (int i = 0; i < 4; i++)
#pragma unroll
        for (int j = 0; j < 4; j++)
#pragma unroll
            for (int q = 0; q < 4; q++) acc[i][j][q] = 0.f;

    load(0); load(1); load(2); load(3);

    int slot = 0, lslot = 4;
    for (int c = 0; c < KT; c++) {
        if (c + 4 <= KT)      CP_WAIT(3);
        else if (c + 3 == KT) CP_WAIT(2);
        else if (c + 2 == KT) CP_WAIT(1);
        else                  CP_WAIT(0);
        __syncthreads();

        if (c + 4 < KT) {
            load(lslot);
            lslot = (lslot == 4) ? 0 : lslot + 1;
        }

        const uint32_t Ab = sb + slot * STAGE;
        const uint32_t Bb = Ab + ABYTES;
#pragma unroll
        for (int ks = 0; ks < 2; ks++) {
            uint32_t a[4][4], b[2][4];
#pragma unroll
            for (int i = 0; i < 4; i++)
                ldsm4(a[i], Ab + ao + (uint32_t)(i * 16 * AROWB + ks * 32));
#pragma unroll
            for (int jj = 0; jj < 2; jj++)
                ldsm4t(b[jj], Bb + bo + (uint32_t)(ks * 16 * BROWB + jj * 32));
#pragma unroll
            for (int i = 0; i < 4; i++)
#pragma unroll
                for (int jj = 0; jj < 2; jj++) {
                    mma_f16(acc[i][2 * jj],     a[i], b[jj][0], b[jj][1]);
                    mma_f16(acc[i][2 * jj + 1], a[i], b[jj][2], b[jj][3]);
                }
        }
        slot = (slot == 4) ? 0 : slot + 1;
    }

    // ---- epilogue ----
    const float* bp = bias + p * NDIM + n0;
    if (LAYER == 1) {
        __half* hb = d_hbuf + (size_t)row0 * HDIM + n0;
#pragma unroll
        for (int j = 0; j < 4; j++) {
            int col = wn * 32 + j * 8 + 2 * tq;
            float bx = bp[col], by = bp[col + 1];
#pragma unroll
            for (int i = 0; i < 4; i++) {
                int r0 = wm * 64 + i * 16 + g;
                __half2 v0 = __floats2half2_rn(fmaxf(acc[i][j][0] + bx, 0.f),
                                               fmaxf(acc[i][j][1] + by, 0.f));
                __half2 v1 = __floats2half2_rn(fmaxf(acc[i][j][2] + bx, 0.f),
                                               fmaxf(acc[i][j][3] + by, 0.f));
                *(__half2*)(hb + (size_t)r0 * HDIM + col)       = v0;
                *(__half2*)(hb + (size_t)(r0 + 8) * HDIM + col) = v1;
            }
        }
        __threadfence();
        __syncthreads();
        if (tid == 0) atomicAdd(&d_ready[t], 1);
    } else {
#pragma unroll
        for (int i = 0; i < 4; i++) {
            int r0 = wm * 64 + i * 16 + g;
            int b0 = rid_s[r0], b1i = rid_s[r0 + 8];
#pragma unroll
            for (int j = 0; j < 4; j++) {
                int col = wn * 32 + j * 8 + 2 * tq;
                float bx = bp[col], by = bp[col + 1];
                if (b0 >= 0)
                    *(float2*)(out + (size_t)b0 * DDIM + n0 + col) =
                        make_float2(acc[i][j][0] + bx, acc[i][j][1] + by);
                if (b1i >= 0)
                    *(float2*)(out + (size_t)b1i * DDIM + n0 + col) =
                        make_float2(acc[i][j][2] + bx, acc[i][j][3] + by);
            }
        }
    }
}

// ---------------- persistent fused dual-layer GEMM, self-resetting ----------------
__global__ __launch_bounds__(256, 2) void k_fused(
    const float* __restrict__ b1, const float* __restrict__ b2,
    float* __restrict__ out)
{
    extern __shared__ char smem[];
    __shared__ int rid_s[128];
    __shared__ int s_item;
    __shared__ int s_last;
    const uint32_t sb = smem_u32(smem);
    const int tid = threadIdx.x;

    int nt = 0;
#pragma unroll
    for (int q = 0; q < PNUM; q++) nt += (d_cursor[q] + 127) >> 7;
    const int NL1 = nt * 8;             // layer-1: 8 n-chunks of 128 over HDIM
    const int NTOT = NL1 + nt * 4;      // layer-2: 4 n-chunks of 128 over DDIM

    while (true) {
        if (tid == 0) s_item = atomicAdd(&d_qhead, 1);
        __syncthreads();
        const int item = s_item;
        __syncthreads();
        if (item >= NTOT) break;
        if (item < NL1) {
            run_item<1>(item >> 3, (item & 7) * 128, b1, out, sb, rid_s);
        } else {
            int j = item - NL1;
            run_item<2>(j >> 2, (j & 3) * 128, b2, out, sb, rid_s);
        }
        __syncthreads();
    }

    // ---- exit: last CTA resets global state for the next graph replay ----
    if (tid == 0) {
        int d = atomicAdd(&d_done, 1);
        s_last = (d == (int)gridDim.x - 1) ? 1 : 0;
    }
    __syncthreads();
    if (s_last) {
        for (int i = tid; i < MAXT; i += 256) d_ready[i] = 0;
        if (tid < PNUM) d_cursor[tid] = 0;
        if (tid == 0) { d_qhead = 0; d_scandone = 0; d_done = 0; }
    }
}

// ---------------- launch ----------------
extern "C" void kernel_launch(void* const* d_in, const int* in_sizes, int n_in,
                              void* d_out, int out_size)
{
    const float* latents = (const float*)d_in[0];
    const float* actions = (const float*)d_in[1];
    const void*  pidx    = d_in[2];
    const float* W1      = (const float*)d_in[3];
    const float* b1      = (const float*)d_in[4];
    const float* W2      = (const float*)d_in[5];
    const float* b2      = (const float*)d_in[6];
    float*       out     = (float*)d_out;

    int B = in_sizes[0] / DDIM;               // 16384
    int scanblk = (B + 255) / 256;            // 64

    int nsm = 148;
    cudaDeviceGetAttribute(&nsm, cudaDevAttrMultiProcessorCount, 0);

    cudaFuncSetAttribute(k_fused, cudaFuncAttributeMaxDynamicSharedMemorySize, SMEM_TOTAL);

    k_scanprep<<<scanblk + W16BLK + GXBLK, 256>>>(
        latents, actions, (const float4*)W1, (const float4*)W2,
        (const int*)pidx, B, scanblk);
    k_fused<<<2 * nsm, 256, SMEM_TOTAL>>>(b1, b2, out);
}